// round 8
// baseline (speedup 1.0000x reference)
#include <cuda_runtime.h>
#include <cstdint>

// Problem constants
constexpr int Bb = 8, Tt = 1024, Dd = 512, Hh = 8, KDk = 64;
constexpr int BT = Bb * Tt;          // 8192
constexpr int HD = Hh * KDk;         // 512
constexpr int OUT_ELEMS = Bb * Tt * Dd;  // offset of attn_weights in d_out

// Scratch (allocation-free: device globals). 16B alignment for float4 access.
__device__ __align__(16) float g_qh[BT * HD];
__device__ __align__(16) float g_kh[BT * HD];
__device__ __align__(16) float g_vh[BT * HD];
__device__ __align__(16) float g_att[BT * HD];

// ---------------------------------------------------------------------------
// tf32 split helpers (3xTF32 scheme): x ~= hi + lo, each tf32.
// ---------------------------------------------------------------------------
__device__ __forceinline__ uint32_t f2tf(float x) {
    uint32_t r; asm("cvt.rna.tf32.f32 %0, %1;" : "=r"(r) : "f"(x)); return r;
}
__device__ __forceinline__ uint2 split2(float x) {
    uint32_t hi = f2tf(x);
    float lo = x - __uint_as_float(hi);
    return make_uint2(hi, f2tf(lo));
}
__device__ __forceinline__ void mma8(float* c, uint32_t a0, uint32_t a1,
                                     uint32_t a2, uint32_t a3,
                                     uint32_t b0, uint32_t b1) {
    asm volatile(
        "mma.sync.aligned.m16n8k8.row.col.f32.tf32.tf32.f32 "
        "{%0,%1,%2,%3},{%4,%5,%6,%7},{%8,%9},{%0,%1,%2,%3};"
        : "+f"(c[0]), "+f"(c[1]), "+f"(c[2]), "+f"(c[3])
        : "r"(a0), "r"(a1), "r"(a2), "r"(a3), "r"(b0), "r"(b1));
}

// ---------------------------------------------------------------------------
// Fragment-packed smem layouts (uint2 = {hi,lo} per element).
// A-pack (m16k8 frags, row-major A): [rowblk16][kstep8][lane][slot0..3]
//   slots per lane t: s0=(t/4, t%4) s1=(t/4+8, t%4) s2=(t/4, t%4+4) s3=(t/4+8, t%4+4)
// B-pack (k8n8 frags, col-major B): [nblk8][kstep8][lane][slot0..1]
//   slots per lane t: s0=(k=t%4, n=t/4) s1=(k=t%4+4, n=t/4)
// Reads are one/two LDS.128 per fragment pair, conflict-free.
// ---------------------------------------------------------------------------
__device__ __forceinline__ int apk_idx(int r, int c) {   // uint2 index
    int rowblk = r >> 4, r16 = r & 15, ks = c >> 3, c8 = c & 7;
    int lane = ((r16 & 7) << 2) | (c8 & 3);
    int slot = ((c8 >> 2) << 1) | (r16 >> 3);
    return ((((rowblk << 2) + ks) << 5) + lane) * 4 + slot;
}
__device__ __forceinline__ int bpk_idx(int k, int n) {   // uint2 index
    int nblk = n >> 3, n8 = n & 7, ks = k >> 3, k8 = k & 7;
    int lane = (n8 << 2) | (k8 & 3);
    int slot = k8 >> 2;
    return ((((nblk << 2) + ks) << 5) + lane) * 2 + slot;
}

// Warp-level MMA over one staged 32-deep k-chunk. Warp tile = MI*16 x NJ*8.
// acc layout: m16n8 C frag: c0=(t/4, 2(t%4)) c1=+1col c2/(c3)=(row+8).
template <int MI, int NJ>
__device__ __forceinline__ void warp_chunk(const uint4* __restrict__ Apk,
                                           const uint4* __restrict__ Bpk,
                                           int wrblk, int wcblk, int lane,
                                           float acc[MI][NJ][4]) {
#pragma unroll
    for (int ks = 0; ks < 4; ks++) {
        uint4 bb[NJ];
#pragma unroll
        for (int nj = 0; nj < NJ; nj++)
            bb[nj] = Bpk[((wcblk + nj) * 4 + ks) * 32 + lane];
#pragma unroll
        for (int mi = 0; mi < MI; mi++) {
            const uint4* ap = &Apk[(((wrblk + mi) * 4 + ks) * 32 + lane) * 2];
            uint4 a0 = ap[0], a1 = ap[1];
            // a_hi = {a0.x,a0.z,a1.x,a1.z}; a_lo = {a0.y,a0.w,a1.y,a1.w}
#pragma unroll
            for (int nj = 0; nj < NJ; nj++) {
                mma8(acc[mi][nj], a0.x, a0.z, a1.x, a1.z, bb[nj].x, bb[nj].z); // hi*hi
                mma8(acc[mi][nj], a0.y, a0.w, a1.y, a1.w, bb[nj].x, bb[nj].z); // lo*hi
                mma8(acc[mi][nj], a0.x, a0.z, a1.x, a1.z, bb[nj].y, bb[nj].w); // hi*lo
            }
        }
    }
}

// ---------------------------------------------------------------------------
// 128x128-tile GEMM, K=512: C = A[8192,512] @ B[512,512]. 8 warps (2x4),
// warp tile 64x32. Staged k-chunks of 32, smem 64KB (A-pack 32K + B-pack 32K).
// ---------------------------------------------------------------------------
__device__ __forceinline__ void gemm512_core(const float* __restrict__ A,
                                             const float* __restrict__ B,
                                             float* __restrict__ C, char* sm) {
    uint2* Apk2 = (uint2*)sm;
    uint2* Bpk2 = (uint2*)(sm + 32768);
    const uint4* Apk4 = (const uint4*)Apk2;
    const uint4* Bpk4 = (const uint4*)Bpk2;

    const int tid = threadIdx.x, lane = tid & 31, warp = tid >> 5;
    const int row0 = blockIdx.y * 128, col0 = blockIdx.x * 128;
    const int wrblk = (warp >> 2) * 4;   // 16-row units
    const int wcblk = (warp & 3) * 4;    // 8-col units

    float acc[4][4][4];
#pragma unroll
    for (int i = 0; i < 4; i++)
#pragma unroll
        for (int j = 0; j < 4; j++)
#pragma unroll
            for (int q = 0; q < 4; q++) acc[i][j][q] = 0.f;

    const int ar = tid >> 1, ac = (tid & 1) * 16;       // A: row, 16 cols
    const int bk = tid >> 3, bn = (tid & 7) * 16;       // B: k-row, 16 cols

    for (int k0 = 0; k0 < 512; k0 += 32) {
        __syncthreads();
        {
            const float* ap = A + (size_t)(row0 + ar) * 512 + k0 + ac;
#pragma unroll
            for (int q = 0; q < 16; q += 4) {
                float4 v = *(const float4*)(ap + q);
                Apk2[apk_idx(ar, ac + q + 0)] = split2(v.x);
                Apk2[apk_idx(ar, ac + q + 1)] = split2(v.y);
                Apk2[apk_idx(ar, ac + q + 2)] = split2(v.z);
                Apk2[apk_idx(ar, ac + q + 3)] = split2(v.w);
            }
            const float* bp = B + (size_t)(k0 + bk) * 512 + col0 + bn;
#pragma unroll
            for (int q = 0; q < 16; q += 4) {
                float4 v = *(const float4*)(bp + q);
                Bpk2[bpk_idx(bk, bn + q + 0)] = split2(v.x);
                Bpk2[bpk_idx(bk, bn + q + 1)] = split2(v.y);
                Bpk2[bpk_idx(bk, bn + q + 2)] = split2(v.z);
                Bpk2[bpk_idx(bk, bn + q + 3)] = split2(v.w);
            }
        }
        __syncthreads();
        warp_chunk<4, 4>(Apk4, Bpk4, wrblk, wcblk, lane, acc);
    }

    const int r0 = row0 + (warp >> 2) * 64 + (lane >> 2);
    const int c0 = col0 + (warp & 3) * 32 + (lane & 3) * 2;
#pragma unroll
    for (int mi = 0; mi < 4; mi++)
#pragma unroll
        for (int nj = 0; nj < 4; nj++) {
            const int r = r0 + mi * 16, c = c0 + nj * 8;
            *(float2*)(C + (size_t)r * 512 + c)       = make_float2(acc[mi][nj][0], acc[mi][nj][1]);
            *(float2*)(C + (size_t)(r + 8) * 512 + c) = make_float2(acc[mi][nj][2], acc[mi][nj][3]);
        }
}

__global__ __launch_bounds__(256)
void proj3_tc(const float* __restrict__ q, const float* __restrict__ k,
              const float* __restrict__ v,
              const float* __restrict__ Wq, const float* __restrict__ Wk,
              const float* __restrict__ Wv,
              float* __restrict__ qh, float* __restrict__ kh,
              float* __restrict__ vh) {
    extern __shared__ char sm[];
    const float* A; const float* Bm; float* C;
    if (blockIdx.z == 0)      { A = q; Bm = Wq; C = qh; }
    else if (blockIdx.z == 1) { A = k; Bm = Wk; C = kh; }
    else                      { A = v; Bm = Wv; C = vh; }
    gemm512_core(A, Bm, C, sm);
}

__global__ __launch_bounds__(256)
void outproj_tc(const float* __restrict__ att, const float* __restrict__ Wo,
                float* __restrict__ out) {
    extern __shared__ char sm[];
    gemm512_core(att, Wo, out, sm);
}

// ---------------------------------------------------------------------------
// RBF weights, tensor-core: per block one 128(q)x128(k) tile of
// W = exp(2*QK^T - |q|^2 - |k|^2). K=64 in 2 chunks of 32. smem 66KB.
// ---------------------------------------------------------------------------
__global__ __launch_bounds__(256)
void rbf_tc(const float* __restrict__ qh, const float* __restrict__ kh,
            float* __restrict__ W) {
    extern __shared__ char sm[];
    uint2* Apk2 = (uint2*)sm;
    uint2* Bpk2 = (uint2*)(sm + 32768);
    const uint4* Apk4 = (const uint4*)Apk2;
    const uint4* Bpk4 = (const uint4*)Bpk2;
    float* q2s = (float*)(sm + 65536);
    float* k2s = q2s + 128;

    const int tid = threadIdx.x, lane = tid & 31, warp = tid >> 5;
    const int kt = blockIdx.x, qt = blockIdx.y, bh = blockIdx.z;
    const int b = bh >> 3, h = bh & 7;

    const float* qbase = qh + (size_t)(b * Tt + qt * 128) * HD + h * 64;
    const float* kbase = kh + (size_t)(b * Tt + kt * 128) * HD + h * 64;

    // Row norms from gmem (fp32)
    if (tid < 128) {
        const float* p = qbase + (size_t)tid * HD;
        float s = 0.f;
#pragma unroll
        for (int c = 0; c < 64; c += 4) {
            float4 x = *(const float4*)(p + c);
            s = fmaf(x.x, x.x, s); s = fmaf(x.y, x.y, s);
            s = fmaf(x.z, x.z, s); s = fmaf(x.w, x.w, s);
        }
        q2s[tid] = s;
    } else {
        const int r = tid - 128;
        const float* p = kbase + (size_t)r * HD;
        float s = 0.f;
#pragma unroll
        for (int c = 0; c < 64; c += 4) {
            float4 x = *(const float4*)(p + c);
            s = fmaf(x.x, x.x, s); s = fmaf(x.y, x.y, s);
            s = fmaf(x.z, x.z, s); s = fmaf(x.w, x.w, s);
        }
        k2s[r] = s;
    }

    const int wrblk = (warp >> 2) * 4;
    const int wcblk = (warp & 3) * 4;

    float acc[4][4][4];
#pragma unroll
    for (int i = 0; i < 4; i++)
#pragma unroll
        for (int j = 0; j < 4; j++)
#pragma unroll
            for (int q = 0; q < 4; q++) acc[i][j][q] = 0.f;

    const int ar = tid >> 1, ac = (tid & 1) * 16;

    for (int k0 = 0; k0 < 64; k0 += 32) {
        __syncthreads();
        {
            const float* ap = qbase + (size_t)ar * HD + k0 + ac;
#pragma unroll
            for (int q = 0; q < 16; q += 4) {
                float4 x = *(const float4*)(ap + q);
                Apk2[apk_idx(ar, ac + q + 0)] = split2(x.x);
                Apk2[apk_idx(ar, ac + q + 1)] = split2(x.y);
                Apk2[apk_idx(ar, ac + q + 2)] = split2(x.z);
                Apk2[apk_idx(ar, ac + q + 3)] = split2(x.w);
            }
            // K-tile: token row -> B-pack column (n), kd -> k
            const float* kp = kbase + (size_t)ar * HD + k0 + ac;
#pragma unroll
            for (int q = 0; q < 16; q += 4) {
                float4 x = *(const float4*)(kp + q);
                Bpk2[bpk_idx(ac + q + 0, ar)] = split2(x.x);
                Bpk2[bpk_idx(ac + q + 1, ar)] = split2(x.y);
                Bpk2[bpk_idx(ac + q + 2, ar)] = split2(x.z);
                Bpk2[bpk_idx(ac + q + 3, ar)] = split2(x.w);
            }
        }
        __syncthreads();
        warp_chunk<4, 4>(Apk4, Bpk4, wrblk, wcblk, lane, acc);
    }

    // Epilogue: exp(2S - q2 - k2) straight from C-fragments
    const int rl0 = (warp >> 2) * 64 + (lane >> 2);
    const int cl0 = (warp & 3) * 32 + (lane & 3) * 2;
    float* wb = W + ((size_t)bh * Tt + qt * 128) * Tt + kt * 128;
#pragma unroll
    for (int mi = 0; mi < 4; mi++)
#pragma unroll
        for (int nj = 0; nj < 4; nj++) {
            const int rl = rl0 + mi * 16, cl = cl0 + nj * 8;
            const float qa = q2s[rl], qb = q2s[rl + 8];
            const float ka = k2s[cl], kb = k2s[cl + 1];
            float2 v0, v1;
            v0.x = __expf(2.f * acc[mi][nj][0] - qa - ka);
            v0.y = __expf(2.f * acc[mi][nj][1] - qa - kb);
            v1.x = __expf(2.f * acc[mi][nj][2] - qb - ka);
            v1.y = __expf(2.f * acc[mi][nj][3] - qb - kb);
            *(float2*)(wb + (size_t)rl * Tt + cl)       = v0;
            *(float2*)(wb + (size_t)(rl + 8) * Tt + cl) = v1;
        }
}

// ---------------------------------------------------------------------------
// attn = W @ V per (b,h): block 128x64, K=1024 in chunks of 32. 8 warps (4x2),
// warp tile 32x32. smem 48KB (A-pack 32K + B-pack 16K).
// ---------------------------------------------------------------------------
__global__ __launch_bounds__(256)
void wv_tc(const float* __restrict__ W, const float* __restrict__ vh,
           float* __restrict__ att) {
    extern __shared__ char sm[];
    uint2* Apk2 = (uint2*)sm;
    uint2* Bpk2 = (uint2*)(sm + 32768);
    const uint4* Apk4 = (const uint4*)Apk2;
    const uint4* Bpk4 = (const uint4*)Bpk2;

    const int tid = threadIdx.x, lane = tid & 31, warp = tid >> 5;
    const int qt = blockIdx.x, bh = blockIdx.y;
    const int b = bh >> 3, h = bh & 7;

    const float* wbase = W + ((size_t)bh * Tt + qt * 128) * Tt;
    const float* vbase = vh + (size_t)(b * Tt) * HD + h * 64;

    const int wrblk = (warp >> 1) * 2;   // 16-row units (32 rows/warp)
    const int wcblk = (warp & 1) * 4;    // 8-col units (32 cols/warp)

    float acc[2][4][4];
#pragma unroll
    for (int i = 0; i < 2; i++)
#pragma unroll
        for (int j = 0; j < 4; j++)
#pragma unroll
            for (int q = 0; q < 4; q++) acc[i][j][q] = 0.f;

    const int ar = tid >> 1, ac = (tid & 1) * 16;   // W staging
    const int vk = tid >> 3, vn = (tid & 7) * 8;    // V staging

    for (int k0 = 0; k0 < Tt; k0 += 32) {
        __syncthreads();
        {
            const float* ap = wbase + (size_t)ar * Tt + k0 + ac;
#pragma unroll
            for (int q = 0; q < 16; q += 4) {
                float4 x = *(const float4*)(ap + q);
                Apk2[apk_idx(ar, ac + q + 0)] = split2(x.x);
                Apk2[apk_idx(ar, ac + q + 1)] = split2(x.y);
                Apk2[apk_idx(ar, ac + q + 2)] = split2(x.z);
                Apk2[apk_idx(ar, ac + q + 3)] = split2(x.w);
            }
            const float* vp = vbase + (size_t)(k0 + vk) * HD + vn;
#pragma unroll
            for (int q = 0; q < 8; q += 4) {
                float4 x = *(const float4*)(vp + q);
                Bpk2[bpk_idx(vk, vn + q + 0)] = split2(x.x);
                Bpk2[bpk_idx(vk, vn + q + 1)] = split2(x.y);
                Bpk2[bpk_idx(vk, vn + q + 2)] = split2(x.z);
                Bpk2[bpk_idx(vk, vn + q + 3)] = split2(x.w);
            }
        }
        __syncthreads();
        warp_chunk<2, 4>(Apk4, Bpk4, wrblk, wcblk, lane, acc);
    }

    const int r0 = (warp >> 1) * 32 + (lane >> 2);
    const int c0 = (warp & 1) * 32 + (lane & 3) * 2;
    float* ob = att + (size_t)(b * Tt + qt * 128) * HD + h * 64;
#pragma unroll
    for (int mi = 0; mi < 2; mi++)
#pragma unroll
        for (int nj = 0; nj < 4; nj++) {
            const int r = r0 + mi * 16, c = c0 + nj * 8;
            *(float2*)(ob + (size_t)r * HD + c)       = make_float2(acc[mi][nj][0], acc[mi][nj][1]);
            *(float2*)(ob + (size_t)(r + 8) * HD + c) = make_float2(acc[mi][nj][2], acc[mi][nj][3]);
        }
}

// ---------------------------------------------------------------------------
extern "C" void kernel_launch(void* const* d_in, const int* in_sizes, int n_in,
                              void* d_out, int out_size) {
    (void)in_sizes; (void)n_in; (void)out_size;

    const float* q  = (const float*)d_in[0];
    const float* k  = (const float*)d_in[1];
    const float* v  = (const float*)d_in[2];
    const float* Wq = (const float*)d_in[3];
    const float* Wk = (const float*)d_in[4];
    const float* Wv = (const float*)d_in[5];
    const float* Wo = (const float*)d_in[6];

    float* out = (float*)d_out;             // [B,T,D]
    float* wts = out + OUT_ELEMS;           // [B,H,T,T]

    void *pq, *pk, *pv, *pa;
    cudaGetSymbolAddress(&pq, g_qh);
    cudaGetSymbolAddress(&pk, g_kh);
    cudaGetSymbolAddress(&pv, g_vh);
    cudaGetSymbolAddress(&pa, g_att);
    float* qh  = (float*)pq;
    float* kh  = (float*)pk;
    float* vh  = (float*)pv;
    float* att = (float*)pa;

    // Raise dynamic smem limits (idempotent; not a stream op)
    cudaFuncSetAttribute(proj3_tc,   cudaFuncAttributeMaxDynamicSharedMemorySize, 65536);
    cudaFuncSetAttribute(outproj_tc, cudaFuncAttributeMaxDynamicSharedMemorySize, 65536);
    cudaFuncSetAttribute(rbf_tc,     cudaFuncAttributeMaxDynamicSharedMemorySize, 66560);
    cudaFuncSetAttribute(wv_tc,      cudaFuncAttributeMaxDynamicSharedMemorySize, 49152);

    dim3 blk(256);
    proj3_tc<<<dim3(HD / 128, BT / 128, 3), blk, 65536>>>(q, k, v, Wq, Wk, Wv, qh, kh, vh);
    rbf_tc<<<dim3(Tt / 128, Tt / 128, Bb * Hh), blk, 66560>>>(qh, kh, wts);
    wv_tc<<<dim3(Tt / 128, Bb * Hh), blk, 49152>>>(wts, vh, att);
    outproj_tc<<<dim3(Dd / 128, BT / 128), blk, 65536>>>(att, Wo, out);
}

// round 10
// speedup vs baseline: 2.1358x; 2.1358x over previous
#include <cuda_runtime.h>
#include <cstdint>

constexpr int OUT_ELEMS = 8192 * 512;

// Packed scratch (allocation-free device globals)
__device__ __align__(16) uint2 g_xpk[3ull * 2048 * 2048];   // q,k,v A-pack
__device__ __align__(16) uint2 g_wpk[4ull * 64 * 4096];     // W^T B-pack (Wq,Wk,Wv,Wo)
__device__ __align__(16) uint2 g_qpk[64ull * 32 * 2048];    // qh A-pack per (b,h)
__device__ __align__(16) uint2 g_kpk[64ull * 16 * 4096];    // kh B-pack per (b,h)
__device__ __align__(16) float g_q2[65536];
__device__ __align__(16) float g_k2[65536];
__device__ __align__(16) float g_vhf[8192ull * 512];
__device__ __align__(16) uint2 g_vpk[64ull * 32 * 2048];    // V^T B-pack per (b,h)
__device__ __align__(16) uint2 g_wtpk[67108864ull];         // attn-weights A-pack (537MB)
__device__ __align__(16) uint2 g_atpk[2048ull * 2048];      // att A-pack

#define DEVI __device__ __forceinline__
DEVI uint32_t s2u(const void* p){uint32_t a;asm("{.reg .u64 t; cvta.to.shared.u64 t,%1; cvt.u32.u64 %0,t;}":"=r"(a):"l"(p));return a;}
DEVI uint32_t f2tf(float x){uint32_t r;asm("cvt.rna.tf32.f32 %0,%1;":"=r"(r):"f"(x));return r;}
DEVI uint2 split2(float x){uint32_t h=f2tf(x);return make_uint2(h,f2tf(x-__uint_as_float(h)));}
DEVI void cp16(uint32_t d,const void* s){asm volatile("cp.async.cg.shared.global [%0],[%1],16;"::"r"(d),"l"(s));}
#define CPC() asm volatile("cp.async.commit_group;":::"memory")
#define CPW() asm volatile("cp.async.wait_group 0;":::"memory")

DEVI void mma8(float* c,uint32_t a0,uint32_t a1,uint32_t a2,uint32_t a3,uint32_t b0,uint32_t b1){
    asm volatile("mma.sync.aligned.m16n8k8.row.col.f32.tf32.tf32.f32 "
        "{%0,%1,%2,%3},{%4,%5,%6,%7},{%8,%9},{%0,%1,%2,%3};"
        :"+f"(c[0]),"+f"(c[1]),"+f"(c[2]),"+f"(c[3])
        :"r"(a0),"r"(a1),"r"(a2),"r"(a3),"r"(b0),"r"(b1));
}

// A-pack (64x32 chunk, 2048 uint2 = 16KB), conflict-free half-split layout:
//   blk = (r/16)*4 + (c/8); half = (c%8)/4; lane = ((r%8)<<2)|(c&3); s0 = (r%16)/8
//   uint2 idx p = (blk*2+half)*64 + lane*2 + s0
DEVI void inv_a(int p,int&r,int&c){
    int s0=p&1, l=(p>>1)&31, hf=(p>>6)&1, ks=(p>>7)&3, rb=p>>9;
    r=rb*16+s0*8+(l>>2); c=ks*8+hf*4+(l&3);
}
// B-pack (N x 32 chunk): uint2 idx = ((nblk*4+ks)*32+lane)*2+slot;
//   lane=((n%8)<<2)|(k&3); slot=(k%8)/4
DEVI void inv_b(int p,int&k,int&n){
    int s=p&1, l=(p>>1)&31, ks=(p>>6)&3, nb=p>>8;
    n=nb*8+(l>>2); k=ks*8+(s<<2)+(l&3);
}

// One 32-deep K-chunk of warp-level MMAs. Warp tile 32 x (NJ*8). Pass-major.
template<int NJ>
DEVI void chunk_mma(const uint4* __restrict__ A4,const uint4* __restrict__ B4,
                    int wy,int wx,int lane,float acc[2][NJ][4]){
#pragma unroll
    for(int ks=0;ks<4;ks++){
        uint4 a[2][2], b[NJ];
#pragma unroll
        for(int mi=0;mi<2;mi++){
            const uint4* ap=A4+((wy*2+mi)*4+ks)*64+lane;
            a[mi][0]=ap[0]; a[mi][1]=ap[32];
        }
#pragma unroll
        for(int nj=0;nj<NJ;nj++) b[nj]=B4[((wx*NJ+nj)*4+ks)*32+lane];
#pragma unroll
        for(int mi=0;mi<2;mi++)
#pragma unroll
            for(int nj=0;nj<NJ;nj++)
                mma8(acc[mi][nj],a[mi][0].x,a[mi][0].z,a[mi][1].x,a[mi][1].z,b[nj].x,b[nj].z);
#pragma unroll
        for(int mi=0;mi<2;mi++)
#pragma unroll
            for(int nj=0;nj<NJ;nj++)
                mma8(acc[mi][nj],a[mi][0].y,a[mi][0].w,a[mi][1].y,a[mi][1].w,b[nj].x,b[nj].z);
#pragma unroll
        for(int mi=0;mi<2;mi++)
#pragma unroll
            for(int nj=0;nj<NJ;nj++)
                mma8(acc[mi][nj],a[mi][0].x,a[mi][0].z,a[mi][1].x,a[mi][1].z,b[nj].y,b[nj].w);
    }
}

template<int NJ,int STRIDE>
DEVI void acc2ep(float* ep,int wy,int wx,int lane,float acc[2][NJ][4]){
#pragma unroll
    for(int mi=0;mi<2;mi++)
#pragma unroll
        for(int nj=0;nj<NJ;nj++){
            int r=wy*32+(lane>>2)+mi*16, c=wx*(NJ*8)+nj*8+(lane&3)*2;
            ep[r*STRIDE+c]=acc[mi][nj][0];     ep[r*STRIDE+c+1]=acc[mi][nj][1];
            ep[(r+8)*STRIDE+c]=acc[mi][nj][2]; ep[(r+8)*STRIDE+c+1]=acc[mi][nj][3];
        }
}

// ------------------------- pack kernels -------------------------
__global__ void pack_x(const float* __restrict__ q,const float* __restrict__ k,
                       const float* __restrict__ v){
    __shared__ float t[64][36];
    const float* src=blockIdx.z==0?q:(blockIdx.z==1?k:v);
    const int m0=blockIdx.y, k0=blockIdx.x, tid=threadIdx.x;
#pragma unroll
    for(int i=0;i<2;i++){
        int r=(tid>>3)+i*32, c4=(tid&7)<<2;
        float4 x=*(const float4*)(src+(size_t)(m0*64+r)*512+k0*32+c4);
        t[r][c4]=x.x; t[r][c4+1]=x.y; t[r][c4+2]=x.z; t[r][c4+3]=x.w;
    }
    __syncthreads();
    uint2* dst=g_xpk+((size_t)(blockIdx.z*128+m0)*16+k0)*2048;
#pragma unroll
    for(int j=0;j<8;j+=2){
        int p=tid*8+j,r,c,r1,c1;
        inv_a(p,r,c); inv_a(p+1,r1,c1);
        uint2 w0=split2(t[r][c]), w1=split2(t[r1][c1]);
        *(uint4*)(dst+p)=make_uint4(w0.x,w0.y,w1.x,w1.y);
    }
}
__global__ void pack_w(const float* __restrict__ Wq,const float* __restrict__ Wk,
                       const float* __restrict__ Wv,const float* __restrict__ Wo){
    __shared__ float t[32][132];
    const float* W=blockIdx.z==0?Wq:(blockIdx.z==1?Wk:(blockIdx.z==2?Wv:Wo));
    const int k0=blockIdx.x, n0=blockIdx.y, tid=threadIdx.x;
#pragma unroll
    for(int i=0;i<4;i++){
        int idx=tid+i*256, r=idx>>5, c4=(idx&31)<<2;
        float4 x=*(const float4*)(W+(size_t)(k0*32+r)*512+n0*128+c4);
        t[r][c4]=x.x; t[r][c4+1]=x.y; t[r][c4+2]=x.z; t[r][c4+3]=x.w;
    }
    __syncthreads();
    uint2* dst=g_wpk+((size_t)(blockIdx.z*4+n0)*16+k0)*4096;
#pragma unroll
    for(int j=0;j<16;j+=2){
        int p=tid*16+j,k,n,k1,n1;
        inv_b(p,k,n); inv_b(p+1,k1,n1);
        uint2 w0=split2(t[k][n]), w1=split2(t[k1][n1]);
        *(uint4*)(dst+p)=make_uint4(w0.x,w0.y,w1.x,w1.y);
    }
}
__global__ void pack_vt(){
    __shared__ float t[32][68];
    const int c0=blockIdx.x, bh=blockIdx.y, b=bh>>3, h=bh&7, tid=threadIdx.x;
#pragma unroll
    for(int i=0;i<2;i++){
        int idx=tid+i*256, r=idx>>4, c4=(idx&15)<<2;
        float4 x=*(const float4*)(g_vhf+(size_t)(b*1024+c0*32+r)*512+h*64+c4);
        t[r][c4]=x.x; t[r][c4+1]=x.y; t[r][c4+2]=x.z; t[r][c4+3]=x.w;
    }
    __syncthreads();
    uint2* dst=g_vpk+((size_t)bh*32+c0)*2048;
#pragma unroll
    for(int j=0;j<8;j+=2){
        int p=tid*8+j,k,n,k1,n1;
        inv_b(p,k,n); inv_b(p+1,k1,n1);
        uint2 w0=split2(t[k][n]), w1=split2(t[k1][n1]);
        *(uint4*)(dst+p)=make_uint4(w0.x,w0.y,w1.x,w1.y);
    }
}

// ------------------------- proj (q,k,v @ W) -------------------------
// block 64x128, K=512 (16 chunks). z=0: qh->A-pack + q2; z=1: kh->B-pack + k2; z=2: vh fp32.
__global__ __launch_bounds__(256,2) void proj_tc(){
    extern __shared__ __align__(16) char sm[];
    const int tid=threadIdx.x, lane=tid&31, warp=tid>>5, wy=warp>>2, wx=warp&3;
    const int bx=blockIdx.x, by=blockIdx.y, z=blockIdx.z;
    const uint32_t smb=s2u(sm);
    const uint4* Ag=(const uint4*)g_xpk+((size_t)(z*128+by)*16)*1024;
    const uint4* Bg=(const uint4*)g_wpk+((size_t)(z*4+bx)*16)*2048;
    float acc[2][4][4];
#pragma unroll
    for(int i=0;i<2;i++)
#pragma unroll
        for(int j=0;j<4;j++)
#pragma unroll
            for(int q2=0;q2<4;q2++) acc[i][j][q2]=0.f;
    auto stage=[&](int c,int bs){
        uint32_t Ad=smb+bs*49152, Bd=Ad+16384;
#pragma unroll
        for(int i=0;i<4;i++) cp16(Ad+(tid+i*256)*16, Ag+(size_t)c*1024+tid+i*256);
#pragma unroll
        for(int i=0;i<8;i++) cp16(Bd+(tid+i*256)*16, Bg+(size_t)c*2048+tid+i*256);
        CPC();
    };
    stage(0,0); CPW(); __syncthreads();
    for(int c=0;c<16;c++){
        if(c<15) stage(c+1,(c+1)&1);
        chunk_mma<4>((const uint4*)(sm+(c&1)*49152),(const uint4*)(sm+(c&1)*49152+16384),wy,wx,lane,acc);
        CPW(); __syncthreads();
    }
    float* ep=(float*)sm;
    acc2ep<4,132>(ep,wy,wx,lane,acc);
    __syncthreads();
    if(z==2){
#pragma unroll
        for(int i=0;i<8;i++){
            int idx=tid+i*256, r=idx>>5, c4=(idx&31)<<2;
            *(float4*)(g_vhf+(size_t)(by*64+r)*512+bx*128+c4)=*(float4*)&ep[r*132+c4];
        }
    } else {
        const int b=by>>4, t0=(by&15)*64, h0=bx*2;
        if(tid<128){
            int r=tid&63, hl=tid>>6;
            float s=0.f;
#pragma unroll
            for(int j=0;j<64;j++){float vv=ep[r*132+hl*64+j]; s=fmaf(vv,vv,s);}
            (z==0?g_q2:g_k2)[(size_t)(b*8+h0+hl)*1024+t0+r]=s;
        }
        if(z==0){
#pragma unroll
            for(int ch=0;ch<4;ch++){
                int hl=ch>>1, kk=ch&1;
                uint2* dst=g_qpk+(((size_t)(b*8+h0+hl)*16+(by&15))*2+kk)*2048;
#pragma unroll
                for(int j=0;j<8;j+=2){
                    int p=tid*8+j,r,c,r1,c1;
                    inv_a(p,r,c); inv_a(p+1,r1,c1);
                    uint2 w0=split2(ep[r*132+hl*64+kk*32+c]);
                    uint2 w1=split2(ep[r1*132+hl*64+kk*32+c1]);
                    *(uint4*)(dst+p)=make_uint4(w0.x,w0.y,w1.x,w1.y);
                }
            }
        } else {
            const int n0=t0>>7, hs=(t0>>6)&1;
#pragma unroll
            for(int ch=0;ch<4;ch++){
                int hl=ch>>1, kk=ch&1;
                uint2* dst=g_kpk+(((size_t)(b*8+h0+hl)*8+n0)*2+kk)*4096+hs*2048;
#pragma unroll
                for(int j=0;j<8;j+=2){
                    int p=tid*8+j,k,n,k1,n1;
                    inv_b(p,k,n); inv_b(p+1,k1,n1);
                    uint2 w0=split2(ep[n*132+hl*64+kk*32+k]);
                    uint2 w1=split2(ep[n1*132+hl*64+kk*32+k1]);
                    *(uint4*)(dst+p)=make_uint4(w0.x,w0.y,w1.x,w1.y);
                }
            }
        }
    }
}

// ------------------------- rbf: W = exp(2QK^T - |q|^2 - |k|^2) -------------------------
// block 64(q) x 128(k), K=64 (2 chunks staged once).
__global__ __launch_bounds__(256,2) void rbf_tc(float* __restrict__ wts){
    extern __shared__ __align__(16) char sm[];
    const int tid=threadIdx.x, lane=tid&31, warp=tid>>5, wy=warp>>2, wx=warp&3;
    const int kt=blockIdx.x, qt=blockIdx.y, bh=blockIdx.z;
    const uint32_t smb=s2u(sm);
    float* q2s=(float*)(sm+98304); float* k2s=q2s+64;
    const uint4* Ag=(const uint4*)g_qpk+((size_t)(bh*16+qt)*2)*1024;
    const uint4* Bg=(const uint4*)g_kpk+((size_t)(bh*8+kt)*2)*2048;
#pragma unroll
    for(int kk=0;kk<2;kk++){
#pragma unroll
        for(int i=0;i<4;i++) cp16(smb+kk*16384+(tid+i*256)*16, Ag+(size_t)kk*1024+tid+i*256);
#pragma unroll
        for(int i=0;i<8;i++) cp16(smb+32768+kk*32768+(tid+i*256)*16, Bg+(size_t)kk*2048+tid+i*256);
    }
    CPC();
    if(tid<64) q2s[tid]=g_q2[(size_t)bh*1024+qt*64+tid];
    else if(tid<192) k2s[tid-64]=g_k2[(size_t)bh*1024+kt*128+tid-64];
    CPW(); __syncthreads();
    float acc[2][4][4];
#pragma unroll
    for(int i=0;i<2;i++)
#pragma unroll
        for(int j=0;j<4;j++)
#pragma unroll
            for(int q2=0;q2<4;q2++) acc[i][j][q2]=0.f;
    chunk_mma<4>((const uint4*)sm,(const uint4*)(sm+32768),wy,wx,lane,acc);
    chunk_mma<4>((const uint4*)(sm+16384),(const uint4*)(sm+65536),wy,wx,lane,acc);
    // exp epilogue on fragments
#pragma unroll
    for(int mi=0;mi<2;mi++)
#pragma unroll
        for(int nj=0;nj<4;nj++){
            int r=wy*32+(lane>>2)+mi*16, c=wx*32+nj*8+(lane&3)*2;
            acc[mi][nj][0]=__expf(2.f*acc[mi][nj][0]-q2s[r]-k2s[c]);
            acc[mi][nj][1]=__expf(2.f*acc[mi][nj][1]-q2s[r]-k2s[c+1]);
            acc[mi][nj][2]=__expf(2.f*acc[mi][nj][2]-q2s[r+8]-k2s[c]);
            acc[mi][nj][3]=__expf(2.f*acc[mi][nj][3]-q2s[r+8]-k2s[c+1]);
        }
    __syncthreads();
    float* ep=(float*)sm;
    acc2ep<4,132>(ep,wy,wx,lane,acc);
    __syncthreads();
    float* wb=wts+((size_t)bh*1024+qt*64)*1024+kt*128;
#pragma unroll
    for(int i=0;i<8;i++){
        int idx=tid+i*256, r=idx>>5, c4=(idx&31)<<2;
        *(float4*)(wb+(size_t)r*1024+c4)=*(float4*)&ep[r*132+c4];
    }
#pragma unroll
    for(int cc=0;cc<4;cc++){
        uint2* dst=g_wtpk+(((size_t)(bh*16+qt))*32+kt*4+cc)*2048;
#pragma unroll
        for(int j=0;j<8;j+=2){
            int p=tid*8+j,r,c,r1,c1;
            inv_a(p,r,c); inv_a(p+1,r1,c1);
            uint2 w0=split2(ep[r*132+cc*32+c]);
            uint2 w1=split2(ep[r1*132+cc*32+c1]);
            *(uint4*)(dst+p)=make_uint4(w0.x,w0.y,w1.x,w1.y);
        }
    }
}

// ------------------------- wv: att = W @ V -------------------------
// block 64x64, K=1024 (32 chunks), double-buffered. Epilogue emits att A-packed.
__global__ __launch_bounds__(256,3) void wv_tc(){
    extern __shared__ __align__(16) char sm[];
    const int tid=threadIdx.x, lane=tid&31, warp=tid>>5, wy=warp>>2, wx=warp&3;
    const int qt=blockIdx.x, bh=blockIdx.y;
    const uint32_t smb=s2u(sm);
    const uint4* Ag=(const uint4*)g_wtpk+((size_t)(bh*16+qt)*32)*1024;
    const uint4* Bg=(const uint4*)g_vpk+((size_t)bh*32)*1024;
    float acc[2][2][4];
#pragma unroll
    for(int i=0;i<2;i++)
#pragma unroll
        for(int j=0;j<2;j++)
#pragma unroll
            for(int q2=0;q2<4;q2++) acc[i][j][q2]=0.f;
    auto stage=[&](int c,int bs){
        uint32_t base=smb+bs*32768;
#pragma unroll
        for(int i=0;i<4;i++) cp16(base+(tid+i*256)*16, Ag+(size_t)c*1024+tid+i*256);
#pragma unroll
        for(int i=0;i<4;i++) cp16(base+16384+(tid+i*256)*16, Bg+(size_t)c*1024+tid+i*256);
        CPC();
    };
    stage(0,0); CPW(); __syncthreads();
    for(int c=0;c<32;c++){
        if(c<31) stage(c+1,(c+1)&1);
        chunk_mma<2>((const uint4*)(sm+(c&1)*32768),(const uint4*)(sm+(c&1)*32768+16384),wy,wx,lane,acc);
        CPW(); __syncthreads();
    }
    float* ep=(float*)sm;
    acc2ep<2,68>(ep,wy,wx,lane,acc);
    __syncthreads();
    const int b=bh>>3, h=bh&7;
#pragma unroll
    for(int cc=0;cc<2;cc++){
        uint2* dst=g_atpk+(((size_t)(b*16+qt))*16+h*2+cc)*2048;
#pragma unroll
        for(int j=0;j<8;j+=2){
            int p=tid*8+j,r,c,r1,c1;
            inv_a(p,r,c); inv_a(p+1,r1,c1);
            uint2 w0=split2(ep[r*68+cc*32+c]);
            uint2 w1=split2(ep[r1*68+cc*32+c1]);
            *(uint4*)(dst+p)=make_uint4(w0.x,w0.y,w1.x,w1.y);
        }
    }
}

// ------------------------- outproj: out = att @ Wo -------------------------
__global__ __launch_bounds__(256,2) void outproj_tc(float* __restrict__ out){
    extern __shared__ __align__(16) char sm[];
    const int tid=threadIdx.x, lane=tid&31, warp=tid>>5, wy=warp>>2, wx=warp&3;
    const int bx=blockIdx.x, by=blockIdx.y;
    const uint32_t smb=s2u(sm);
    const uint4* Ag=(const uint4*)g_atpk+((size_t)by*16)*1024;
    const uint4* Bg=(const uint4*)g_wpk+((size_t)(12+bx)*16)*2048;
    float acc[2][4][4];
#pragma unroll
    for(int i=0;i<2;i++)
#pragma unroll
        for(int j=0;j<4;j++)
#pragma unroll
            for(int q2=0;q2<4;q2++) acc[i][j][q2]=0.f;
    auto stage=[&](int c,int bs){
        uint32_t Ad=smb+bs*49152, Bd=Ad+16384;
#pragma unroll
        for(int i=0;i<4;i++) cp16(Ad+(tid+i*256)*16, Ag+(size_t)c*1024+tid+i*256);
#pragma unroll
        for(int i=0;i<8;i++) cp16(Bd+(tid+i*256)*16, Bg+(size_t)c*2048+tid+i*256);
        CPC();
    };
    stage(0,0); CPW(); __syncthreads();
    for(int c=0;c<16;c++){
        if(c<15) stage(c+1,(c+1)&1);
        chunk_mma<4>((const uint4*)(sm+(c&1)*49152),(const uint4*)(sm+(c&1)*49152+16384),wy,wx,lane,acc);
        CPW(); __syncthreads();
    }
    float* ep=(float*)sm;
    acc2ep<4,132>(ep,wy,wx,lane,acc);
    __syncthreads();
#pragma unroll
    for(int i=0;i<8;i++){
        int idx=tid+i*256, r=idx>>5, c4=(idx&31)<<2;
        *(float4*)(out+(size_t)(by*64+r)*512+bx*128+c4)=*(float4*)&ep[r*132+c4];
    }
}

// ---------------------------------------------------------------------------
extern "C" void kernel_launch(void* const* d_in,const int* in_sizes,int n_in,
                              void* d_out,int out_size){
    (void)in_sizes; (void)n_in; (void)out_size;
    const float* q =(const float*)d_in[0];
    const float* k =(const float*)d_in[1];
    const float* v =(const float*)d_in[2];
    const float* Wq=(const float*)d_in[3];
    const float* Wk=(const float*)d_in[4];
    const float* Wv=(const float*)d_in[5];
    const float* Wo=(const float*)d_in[6];
    float* out=(float*)d_out;
    float* wts=out+OUT_ELEMS;

    cudaFuncSetAttribute(proj_tc,    cudaFuncAttributeMaxDynamicSharedMemorySize, 98304);
    cudaFuncSetAttribute(outproj_tc, cudaFuncAttributeMaxDynamicSharedMemorySize, 98304);
    cudaFuncSetAttribute(rbf_tc,     cudaFuncAttributeMaxDynamicSharedMemorySize, 99072);
    cudaFuncSetAttribute(wv_tc,      cudaFuncAttributeMaxDynamicSharedMemorySize, 65536);

    pack_x<<<dim3(16,128,3),256>>>(q,k,v);
    pack_w<<<dim3(16,4,4),256>>>(Wq,Wk,Wv,Wo);
    proj_tc<<<dim3(4,128,3),256,98304>>>();
    pack_vt<<<dim3(32,64),256>>>();
    rbf_tc<<<dim3(8,16,64),256,99072>>>(wts);
    wv_tc<<<dim3(16,64),256,65536>>>();
    outproj_tc<<<dim3(4,128),256,98304>>>(out);
}

// round 11
// speedup vs baseline: 2.8035x; 1.3126x over previous
#include <cuda_runtime.h>
#include <cstdint>

constexpr int OUT_ELEMS = 8192 * 512;

// Packed scratch (allocation-free device globals)
__device__ __align__(16) uint2    g_xpk[3ull * 2048 * 2048];   // q,k,v A-pack (split)
__device__ __align__(16) uint2    g_wpk[4ull * 64 * 4096];     // Wq,Wk,Wv B-pack (split)
__device__ __align__(16) uint2    g_qpk[64ull * 32 * 2048];    // qh A-pack per (b,h)
__device__ __align__(16) uint2    g_kpk[64ull * 16 * 4096];    // kh B-pack per (b,h)
__device__ __align__(16) float    g_q2[65536];
__device__ __align__(16) float    g_k2[65536];
__device__ __align__(16) float    g_vhf[8192ull * 512];
__device__ __align__(16) uint32_t g_vpkh[64ull * 32 * 2048];   // V^T B-pack, tf32-hi only
__device__ __align__(16) uint32_t g_atpkh[8192ull * 512];      // att A-pack, tf32-hi only
__device__ __align__(16) uint32_t g_wohpk[4ull * 16 * 4096];   // Wo B-pack, tf32-hi only

#define DEVI __device__ __forceinline__
DEVI uint32_t s2u(const void* p){uint32_t a;asm("{.reg .u64 t; cvta.to.shared.u64 t,%1; cvt.u32.u64 %0,t;}":"=r"(a):"l"(p));return a;}
DEVI uint32_t f2tf(float x){uint32_t r;asm("cvt.rna.tf32.f32 %0,%1;":"=r"(r):"f"(x));return r;}
DEVI uint2 split2(float x){uint32_t h=f2tf(x);return make_uint2(h,f2tf(x-__uint_as_float(h)));}
DEVI void cp16(uint32_t d,const void* s){asm volatile("cp.async.cg.shared.global [%0],[%1],16;"::"r"(d),"l"(s));}
#define CPC() asm volatile("cp.async.commit_group;":::"memory")
#define CPW() asm volatile("cp.async.wait_group 0;":::"memory")

DEVI void mma8(float* c,uint32_t a0,uint32_t a1,uint32_t a2,uint32_t a3,uint32_t b0,uint32_t b1){
    asm volatile("mma.sync.aligned.m16n8k8.row.col.f32.tf32.tf32.f32 "
        "{%0,%1,%2,%3},{%4,%5,%6,%7},{%8,%9},{%0,%1,%2,%3};"
        :"+f"(c[0]),"+f"(c[1]),"+f"(c[2]),"+f"(c[3])
        :"r"(a0),"r"(a1),"r"(a2),"r"(a3),"r"(b0),"r"(b1));
}

// Split A-pack (uint2/elem) and B-pack inverse index maps (as R9, verified)
DEVI void inv_a(int p,int&r,int&c){
    int s0=p&1, l=(p>>1)&31, hf=(p>>6)&1, ks=(p>>7)&3, rb=p>>9;
    r=rb*16+s0*8+(l>>2); c=ks*8+hf*4+(l&3);
}
DEVI void inv_b(int p,int&k,int&n){
    int s=p&1, l=(p>>1)&31, ks=(p>>6)&3, nb=p>>8;
    n=nb*8+(l>>2); k=ks*8+(s<<2)+(l&3);
}
// Hi-only A-pack (1 word/elem): word = ((rb*4+ks)*32+lane)*4+slot
DEVI void inv_ah(int p,int&r,int&c){
    int s=p&3, l=(p>>2)&31, ks=(p>>7)&3, rb=p>>9;
    r=rb*16+(s&1)*8+(l>>2); c=ks*8+((s>>1)<<2)+(l&3);
}

// Split 3-pass chunk (MI=2), pass-major — identical to R9 (verified)
template<int NJ>
DEVI void chunk_mma(const uint4* __restrict__ A4,const uint4* __restrict__ B4,
                    int wy,int wx,int lane,float acc[2][NJ][4]){
#pragma unroll
    for(int ks=0;ks<4;ks++){
        uint4 a[2][2], b[NJ];
#pragma unroll
        for(int mi=0;mi<2;mi++){
            const uint4* ap=A4+((wy*2+mi)*4+ks)*64+lane;
            a[mi][0]=ap[0]; a[mi][1]=ap[32];
        }
#pragma unroll
        for(int nj=0;nj<NJ;nj++) b[nj]=B4[((wx*NJ+nj)*4+ks)*32+lane];
#pragma unroll
        for(int mi=0;mi<2;mi++)
#pragma unroll
            for(int nj=0;nj<NJ;nj++)
                mma8(acc[mi][nj],a[mi][0].x,a[mi][0].z,a[mi][1].x,a[mi][1].z,b[nj].x,b[nj].z);
#pragma unroll
        for(int mi=0;mi<2;mi++)
#pragma unroll
            for(int nj=0;nj<NJ;nj++)
                mma8(acc[mi][nj],a[mi][0].y,a[mi][0].w,a[mi][1].y,a[mi][1].w,b[nj].x,b[nj].z);
#pragma unroll
        for(int mi=0;mi<2;mi++)
#pragma unroll
            for(int nj=0;nj<NJ;nj++)
                mma8(acc[mi][nj],a[mi][0].x,a[mi][0].z,a[mi][1].x,a[mi][1].z,b[nj].y,b[nj].w);
    }
}

// Hi-only 1-pass chunk (MI=2)
template<int NJ>
DEVI void chunk_mma_hi(const uint4* __restrict__ A4,const uint2* __restrict__ B2,
                       int wy,int wx,int lane,float acc[2][NJ][4]){
#pragma unroll
    for(int ks=0;ks<4;ks++){
        uint4 a[2]; uint2 b[NJ];
#pragma unroll
        for(int mi=0;mi<2;mi++) a[mi]=A4[((wy*2+mi)*4+ks)*32+lane];
#pragma unroll
        for(int nj=0;nj<NJ;nj++) b[nj]=B2[((wx*NJ+nj)*4+ks)*32+lane];
#pragma unroll
        for(int mi=0;mi<2;mi++)
#pragma unroll
            for(int nj=0;nj<NJ;nj++)
                mma8(acc[mi][nj],a[mi].x,a[mi].y,a[mi].z,a[mi].w,b[nj].x,b[nj].y);
    }
}

template<int NJ,int STRIDE>
DEVI void acc2ep(float* ep,int wy,int wx,int lane,float acc[2][NJ][4]){
#pragma unroll
    for(int mi=0;mi<2;mi++)
#pragma unroll
        for(int nj=0;nj<NJ;nj++){
            int r=wy*32+(lane>>2)+mi*16, c=wx*(NJ*8)+nj*8+(lane&3)*2;
            ep[r*STRIDE+c]=acc[mi][nj][0];     ep[r*STRIDE+c+1]=acc[mi][nj][1];
            ep[(r+8)*STRIDE+c]=acc[mi][nj][2]; ep[(r+8)*STRIDE+c+1]=acc[mi][nj][3];
        }
}

// ------------------------- pack kernels -------------------------
__global__ void pack_x(const float* __restrict__ q,const float* __restrict__ k,
                       const float* __restrict__ v){
    __shared__ float t[64][36];
    const float* src=blockIdx.z==0?q:(blockIdx.z==1?k:v);
    const int m0=blockIdx.y, k0=blockIdx.x, tid=threadIdx.x;
#pragma unroll
    for(int i=0;i<2;i++){
        int r=(tid>>3)+i*32, c4=(tid&7)<<2;
        float4 x=*(const float4*)(src+(size_t)(m0*64+r)*512+k0*32+c4);
        t[r][c4]=x.x; t[r][c4+1]=x.y; t[r][c4+2]=x.z; t[r][c4+3]=x.w;
    }
    __syncthreads();
    uint2* dst=g_xpk+((size_t)(blockIdx.z*128+m0)*16+k0)*2048;
#pragma unroll
    for(int j=0;j<8;j+=2){
        int p=tid*8+j,r,c,r1,c1;
        inv_a(p,r,c); inv_a(p+1,r1,c1);
        uint2 w0=split2(t[r][c]), w1=split2(t[r1][c1]);
        *(uint4*)(dst+p)=make_uint4(w0.x,w0.y,w1.x,w1.y);
    }
}
__global__ void pack_w(const float* __restrict__ Wq,const float* __restrict__ Wk,
                       const float* __restrict__ Wv){
    __shared__ float t[32][132];
    const float* W=blockIdx.z==0?Wq:(blockIdx.z==1?Wk:Wv);
    const int k0=blockIdx.x, n0=blockIdx.y, tid=threadIdx.x;
#pragma unroll
    for(int i=0;i<4;i++){
        int idx=tid+i*256, r=idx>>5, c4=(idx&31)<<2;
        float4 x=*(const float4*)(W+(size_t)(k0*32+r)*512+n0*128+c4);
        t[r][c4]=x.x; t[r][c4+1]=x.y; t[r][c4+2]=x.z; t[r][c4+3]=x.w;
    }
    __syncthreads();
    uint2* dst=g_wpk+((size_t)(blockIdx.z*4+n0)*16+k0)*4096;
#pragma unroll
    for(int j=0;j<16;j+=2){
        int p=tid*16+j,k,n,k1,n1;
        inv_b(p,k,n); inv_b(p+1,k1,n1);
        uint2 w0=split2(t[k][n]), w1=split2(t[k1][n1]);
        *(uint4*)(dst+p)=make_uint4(w0.x,w0.y,w1.x,w1.y);
    }
}
__global__ void pack_woh(const float* __restrict__ Wo){
    __shared__ float t[32][132];
    const int k0=blockIdx.x, n0=blockIdx.y, tid=threadIdx.x;
#pragma unroll
    for(int i=0;i<4;i++){
        int idx=tid+i*256, r=idx>>5, c4=(idx&31)<<2;
        float4 x=*(const float4*)(Wo+(size_t)(k0*32+r)*512+n0*128+c4);
        t[r][c4]=x.x; t[r][c4+1]=x.y; t[r][c4+2]=x.z; t[r][c4+3]=x.w;
    }
    __syncthreads();
    uint32_t* dst=g_wohpk+((size_t)(n0*16+k0))*4096;
#pragma unroll
    for(int j=0;j<16;j+=2){
        int p=tid*16+j,k,n,k1,n1;
        inv_b(p,k,n); inv_b(p+1,k1,n1);
        *(uint2*)(dst+p)=make_uint2(f2tf(t[k][n]),f2tf(t[k1][n1]));
    }
}
__global__ void pack_vt(){
    __shared__ float t[32][68];
    const int c0=blockIdx.x, bh=blockIdx.y, b=bh>>3, h=bh&7, tid=threadIdx.x;
#pragma unroll
    for(int i=0;i<2;i++){
        int idx=tid+i*256, r=idx>>4, c4=(idx&15)<<2;
        float4 x=*(const float4*)(g_vhf+(size_t)(b*1024+c0*32+r)*512+h*64+c4);
        t[r][c4]=x.x; t[r][c4+1]=x.y; t[r][c4+2]=x.z; t[r][c4+3]=x.w;
    }
    __syncthreads();
    uint32_t* dst=g_vpkh+((size_t)bh*32+c0)*2048;
#pragma unroll
    for(int j=0;j<8;j+=2){
        int p=tid*8+j,k,n,k1,n1;
        inv_b(p,k,n); inv_b(p+1,k1,n1);
        *(uint2*)(dst+p)=make_uint2(f2tf(t[k][n]),f2tf(t[k1][n1]));
    }
}

// ------------------------- proj (q,k,v @ W), 3-pass — R9 verbatim -------------------------
__global__ __launch_bounds__(256,2) void proj_tc(){
    extern __shared__ __align__(16) char sm[];
    const int tid=threadIdx.x, lane=tid&31, warp=tid>>5, wy=warp>>2, wx=warp&3;
    const int bx=blockIdx.x, by=blockIdx.y, z=blockIdx.z;
    const uint32_t smb=s2u(sm);
    const uint4* Ag=(const uint4*)g_xpk+((size_t)(z*128+by)*16)*1024;
    const uint4* Bg=(const uint4*)g_wpk+((size_t)(z*4+bx)*16)*2048;
    float acc[2][4][4];
#pragma unroll
    for(int i=0;i<2;i++)
#pragma unroll
        for(int j=0;j<4;j++)
#pragma unroll
            for(int q2=0;q2<4;q2++) acc[i][j][q2]=0.f;
    auto stage=[&](int c,int bs){
        uint32_t Ad=smb+bs*49152, Bd=Ad+16384;
#pragma unroll
        for(int i=0;i<4;i++) cp16(Ad+(tid+i*256)*16, Ag+(size_t)c*1024+tid+i*256);
#pragma unroll
        for(int i=0;i<8;i++) cp16(Bd+(tid+i*256)*16, Bg+(size_t)c*2048+tid+i*256);
        CPC();
    };
    stage(0,0); CPW(); __syncthreads();
    for(int c=0;c<16;c++){
        if(c<15) stage(c+1,(c+1)&1);
        chunk_mma<4>((const uint4*)(sm+(c&1)*49152),(const uint4*)(sm+(c&1)*49152+16384),wy,wx,lane,acc);
        CPW(); __syncthreads();
    }
    float* ep=(float*)sm;
    acc2ep<4,132>(ep,wy,wx,lane,acc);
    __syncthreads();
    if(z==2){
#pragma unroll
        for(int i=0;i<8;i++){
            int idx=tid+i*256, r=idx>>5, c4=(idx&31)<<2;
            *(float4*)(g_vhf+(size_t)(by*64+r)*512+bx*128+c4)=*(float4*)&ep[r*132+c4];
        }
    } else {
        const int b=by>>4, t0=(by&15)*64, h0=bx*2;
        if(tid<128){
            int r=tid&63, hl=tid>>6;
            float s=0.f;
#pragma unroll
            for(int j=0;j<64;j++){float vv=ep[r*132+hl*64+j]; s=fmaf(vv,vv,s);}
            (z==0?g_q2:g_k2)[(size_t)(b*8+h0+hl)*1024+t0+r]=s;
        }
        if(z==0){
#pragma unroll
            for(int ch=0;ch<4;ch++){
                int hl=ch>>1, kk=ch&1;
                uint2* dst=g_qpk+(((size_t)(b*8+h0+hl)*16+(by&15))*2+kk)*2048;
#pragma unroll
                for(int j=0;j<8;j+=2){
                    int p=tid*8+j,r,c,r1,c1;
                    inv_a(p,r,c); inv_a(p+1,r1,c1);
                    uint2 w0=split2(ep[r*132+hl*64+kk*32+c]);
                    uint2 w1=split2(ep[r1*132+hl*64+kk*32+c1]);
                    *(uint4*)(dst+p)=make_uint4(w0.x,w0.y,w1.x,w1.y);
                }
            }
        } else {
            const int n0=t0>>7, hs=(t0>>6)&1;
#pragma unroll
            for(int ch=0;ch<4;ch++){
                int hl=ch>>1, kk=ch&1;
                uint2* dst=g_kpk+(((size_t)(b*8+h0+hl)*8+n0)*2+kk)*4096+hs*2048;
#pragma unroll
                for(int j=0;j<8;j+=2){
                    int p=tid*8+j,k,n,k1,n1;
                    inv_b(p,k,n); inv_b(p+1,k1,n1);
                    uint2 w0=split2(ep[n*132+hl*64+kk*32+k]);
                    uint2 w1=split2(ep[n1*132+hl*64+kk*32+k1]);
                    *(uint4*)(dst+p)=make_uint4(w0.x,w0.y,w1.x,w1.y);
                }
            }
        }
    }
}

// ------------------------- rbf (3-pass) — R9 minus the packed-copy epilogue -------------------------
__global__ __launch_bounds__(256,2) void rbf_tc(float* __restrict__ wts){
    extern __shared__ __align__(16) char sm[];
    const int tid=threadIdx.x, lane=tid&31, warp=tid>>5, wy=warp>>2, wx=warp&3;
    const int kt=blockIdx.x, qt=blockIdx.y, bh=blockIdx.z;
    const uint32_t smb=s2u(sm);
    float* q2s=(float*)(sm+98304); float* k2s=q2s+64;
    const uint4* Ag=(const uint4*)g_qpk+((size_t)(bh*16+qt)*2)*1024;
    const uint4* Bg=(const uint4*)g_kpk+((size_t)(bh*8+kt)*2)*2048;
#pragma unroll
    for(int kk=0;kk<2;kk++){
#pragma unroll
        for(int i=0;i<4;i++) cp16(smb+kk*16384+(tid+i*256)*16, Ag+(size_t)kk*1024+tid+i*256);
#pragma unroll
        for(int i=0;i<8;i++) cp16(smb+32768+kk*32768+(tid+i*256)*16, Bg+(size_t)kk*2048+tid+i*256);
    }
    CPC();
    if(tid<64) q2s[tid]=g_q2[(size_t)bh*1024+qt*64+tid];
    else if(tid<192) k2s[tid-64]=g_k2[(size_t)bh*1024+kt*128+tid-64];
    CPW(); __syncthreads();
    float acc[2][4][4];
#pragma unroll
    for(int i=0;i<2;i++)
#pragma unroll
        for(int j=0;j<4;j++)
#pragma unroll
            for(int q2=0;q2<4;q2++) acc[i][j][q2]=0.f;
    chunk_mma<4>((const uint4*)sm,(const uint4*)(sm+32768),wy,wx,lane,acc);
    chunk_mma<4>((const uint4*)(sm+16384),(const uint4*)(sm+65536),wy,wx,lane,acc);
#pragma unroll
    for(int mi=0;mi<2;mi++)
#pragma unroll
        for(int nj=0;nj<4;nj++){
            int r=wy*32+(lane>>2)+mi*16, c=wx*32+nj*8+(lane&3)*2;
            acc[mi][nj][0]=__expf(2.f*acc[mi][nj][0]-q2s[r]-k2s[c]);
            acc[mi][nj][1]=__expf(2.f*acc[mi][nj][1]-q2s[r]-k2s[c+1]);
            acc[mi][nj][2]=__expf(2.f*acc[mi][nj][2]-q2s[r+8]-k2s[c]);
            acc[mi][nj][3]=__expf(2.f*acc[mi][nj][3]-q2s[r+8]-k2s[c+1]);
        }
    __syncthreads();
    float* ep=(float*)sm;
    acc2ep<4,132>(ep,wy,wx,lane,acc);
    __syncthreads();
    float* wb=wts+((size_t)bh*1024+qt*64)*1024+kt*128;
#pragma unroll
    for(int i=0;i<8;i++){
        int idx=tid+i*256, r=idx>>5, c4=(idx&31)<<2;
        *(float4*)(wb+(size_t)r*1024+c4)=*(float4*)&ep[r*132+c4];
    }
}

// ------------------------- wv: att = W @ V, tf32-hi 1-pass -------------------------
// block 64x64, K=1024 (32 chunks), double-buffered. A = fp32 wts cvt'd in-kernel.
// smem: Ahi 2x8K @0, Bhi 2x8K @16384, fstg 2x9216 @32768 (stride-36 rows, bank-spread)
__global__ __launch_bounds__(256,3) void wv_hi(const float* __restrict__ wts){
    extern __shared__ __align__(16) char sm[];
    const int tid=threadIdx.x, lane=tid&31, warp=tid>>5, wy=warp>>2, wx=warp&3;
    const int qt=blockIdx.x, bh=blockIdx.y;
    const uint32_t smb=s2u(sm);
    const float* wb=wts+((size_t)bh*1024+qt*64)*1024;
    const uint4* Bg=(const uint4*)g_vpkh+(size_t)bh*32*512;
    float acc[2][2][4];
#pragma unroll
    for(int i=0;i<2;i++)
#pragma unroll
        for(int j=0;j<2;j++)
#pragma unroll
            for(int q2=0;q2<4;q2++) acc[i][j][q2]=0.f;
    auto stage=[&](int c,int bs){
        uint32_t fd=smb+32768+bs*9216, bd=smb+16384+bs*8192;
#pragma unroll
        for(int i=0;i<2;i++){
            int idx=tid+i*256, r=idx>>3, c4=(idx&7)<<2;
            cp16(fd+(r*36+c4)*4, wb+(size_t)r*1024+c*32+c4);
            cp16(bd+idx*16, Bg+(size_t)c*512+idx);
        }
        CPC();
    };
    auto cvtA=[&](int bs){
        const float* stg=(const float*)(sm+32768+bs*9216);
        uint32_t* dst=(uint32_t*)(sm+bs*8192);
#pragma unroll
        for(int j=0;j<8;j+=4){
            int p=tid*8+j; uint32_t w[4];
#pragma unroll
            for(int jj=0;jj<4;jj++){ int r,cc; inv_ah(p+jj,r,cc); w[jj]=f2tf(stg[r*36+cc]); }
            *(uint4*)(dst+p)=make_uint4(w[0],w[1],w[2],w[3]);
        }
    };
    stage(0,0); CPW(); __syncthreads(); cvtA(0); __syncthreads();
    for(int c=0;c<32;c++){
        if(c<31) stage(c+1,(c+1)&1);
        chunk_mma_hi<2>((const uint4*)(sm+(c&1)*8192),(const uint2*)(sm+16384+(c&1)*8192),wy,wx,lane,acc);
        CPW(); __syncthreads();
        if(c<31) cvtA((c+1)&1);
        __syncthreads();
    }
    float* ep=(float*)sm;
    acc2ep<2,68>(ep,wy,wx,lane,acc);
    __syncthreads();
    const int b=bh>>3, h=bh&7;
#pragma unroll
    for(int cc=0;cc<2;cc++){
        uint32_t* dst=g_atpkh+((size_t)(b*16+qt)*16+h*2+cc)*2048;
#pragma unroll
        for(int j=0;j<8;j+=4){
            int p=tid*8+j; uint32_t w[4];
#pragma unroll
            for(int jj=0;jj<4;jj++){ int r,ccx; inv_ah(p+jj,r,ccx); w[jj]=f2tf(ep[r*68+cc*32+ccx]); }
            *(uint4*)(dst+p)=make_uint4(w[0],w[1],w[2],w[3]);
        }
    }
}

// ------------------------- outproj: out = att @ Wo, tf32-hi 1-pass -------------------------
// block 64x128, K=512 (16 chunks). smem: Ahi 2x8K @0, Bhi 2x16K @16384.
__global__ __launch_bounds__(256,3) void outproj_hi(float* __restrict__ out){
    extern __shared__ __align__(16) char sm[];
    const int tid=threadIdx.x, lane=tid&31, warp=tid>>5, wy=warp>>2, wx=warp&3;
    const int bx=blockIdx.x, by=blockIdx.y;
    const uint32_t smb=s2u(sm);
    const uint4* Ag=(const uint4*)g_atpkh+((size_t)by*16)*512;
    const uint4* Bg=(const uint4*)g_wohpk+((size_t)bx*16)*1024;
    float acc[2][4][4];
#pragma unroll
    for(int i=0;i<2;i++)
#pragma unroll
        for(int j=0;j<4;j++)
#pragma unroll
            for(int q2=0;q2<4;q2++) acc[i][j][q2]=0.f;
    auto stage=[&](int c,int bs){
        uint32_t Ad=smb+bs*8192, Bd=smb+16384+bs*16384;
#pragma unroll
        for(int i=0;i<2;i++) cp16(Ad+(tid+i*256)*16, Ag+(size_t)c*512+tid+i*256);
#pragma unroll
        for(int i=0;i<4;i++) cp16(Bd+(tid+i*256)*16, Bg+(size_t)c*1024+tid+i*256);
        CPC();
    };
    stage(0,0); CPW(); __syncthreads();
    for(int c=0;c<16;c++){
        if(c<15) stage(c+1,(c+1)&1);
        chunk_mma_hi<4>((const uint4*)(sm+(c&1)*8192),(const uint2*)(sm+16384+(c&1)*16384),wy,wx,lane,acc);
        CPW(); __syncthreads();
    }
    float* ep=(float*)sm;
    acc2ep<4,132>(ep,wy,wx,lane,acc);
    __syncthreads();
#pragma unroll
    for(int i=0;i<8;i++){
        int idx=tid+i*256, r=idx>>5, c4=(idx&31)<<2;
        *(float4*)(out+(size_t)(by*64+r)*512+bx*128+c4)=*(float4*)&ep[r*132+c4];
    }
}

// ---------------------------------------------------------------------------
extern "C" void kernel_launch(void* const* d_in,const int* in_sizes,int n_in,
                              void* d_out,int out_size){
    (void)in_sizes; (void)n_in; (void)out_size;
    const float* q =(const float*)d_in[0];
    const float* k =(const float*)d_in[1];
    const float* v =(const float*)d_in[2];
    const float* Wq=(const float*)d_in[3];
    const float* Wk=(const float*)d_in[4];
    const float* Wv=(const float*)d_in[5];
    const float* Wo=(const float*)d_in[6];
    float* out=(float*)d_out;
    float* wts=out+OUT_ELEMS;

    cudaFuncSetAttribute(proj_tc,    cudaFuncAttributeMaxDynamicSharedMemorySize, 98304);
    cudaFuncSetAttribute(rbf_tc,     cudaFuncAttributeMaxDynamicSharedMemorySize, 99072);
    cudaFuncSetAttribute(wv_hi,      cudaFuncAttributeMaxDynamicSharedMemorySize, 51200);
    cudaFuncSetAttribute(outproj_hi, cudaFuncAttributeMaxDynamicSharedMemorySize, 49152);

    pack_x<<<dim3(16,128,3),256>>>(q,k,v);
    pack_w<<<dim3(16,4,3),256>>>(Wq,Wk,Wv);
    pack_woh<<<dim3(16,4),256>>>(Wo);
    proj_tc<<<dim3(4,128,3),256,98304>>>();
    pack_vt<<<dim3(32,64),256>>>();
    rbf_tc<<<dim3(8,16,64),256,99072>>>(wts);
    wv_hi<<<dim3(16,64),256,51200>>>(wts);
    outproj_hi<<<dim3(4,128),256,49152>>>(out);
}

// round 13
// speedup vs baseline: 3.1071x; 1.1083x over previous
#include <cuda_runtime.h>
#include <cstdint>

constexpr int OUT_ELEMS = 8192 * 512;

// Packed scratch (allocation-free device globals)
__device__ __align__(16) uint2    g_xpk[2ull * 2048 * 2048];   // q,k A-pack (split)
__device__ __align__(16) uint32_t g_xpkh[2048ull * 2048];      // v A-pack (hi)
__device__ __align__(16) uint2    g_wpk[2ull * 64 * 4096];     // Wq,Wk B-pack (split)
__device__ __align__(16) uint32_t g_wvhpk[64ull * 4096];       // Wv B-pack (hi)
__device__ __align__(16) uint32_t g_wohpk[64ull * 4096];       // Wo B-pack (hi)
__device__ __align__(16) uint2    g_qpk[64ull * 32 * 2048];    // qh A-pack per (b,h)
__device__ __align__(16) uint2    g_kpk[64ull * 16 * 4096];    // kh B-pack per (b,h)
__device__ __align__(16) float    g_q2[65536];
__device__ __align__(16) float    g_k2[65536];
__device__ __align__(16) float    g_vhf[8192ull * 512];
__device__ __align__(16) uint32_t g_vpkh[64ull * 32 * 2048];   // V^T B-pack (hi)
__device__ __align__(16) uint32_t g_atpkh[8192ull * 512];      // att A-pack (hi)

#define DEVI __device__ __forceinline__
DEVI uint32_t s2u(const void* p){uint32_t a;asm("{.reg .u64 t; cvta.to.shared.u64 t,%1; cvt.u32.u64 %0,t;}":"=r"(a):"l"(p));return a;}
DEVI uint32_t f2tf(float x){uint32_t r;asm("cvt.rna.tf32.f32 %0,%1;":"=r"(r):"f"(x));return r;}
DEVI uint2 split2(float x){uint32_t h=f2tf(x);return make_uint2(h,f2tf(x-__uint_as_float(h)));}
DEVI void cp16(uint32_t d,const void* s){asm volatile("cp.async.cg.shared.global [%0],[%1],16;"::"r"(d),"l"(s));}
#define CPC() asm volatile("cp.async.commit_group;":::"memory")
#define CPW() asm volatile("cp.async.wait_group 0;":::"memory")

DEVI void mma8(float* c,uint32_t a0,uint32_t a1,uint32_t a2,uint32_t a3,uint32_t b0,uint32_t b1){
    asm volatile("mma.sync.aligned.m16n8k8.row.col.f32.tf32.tf32.f32 "
        "{%0,%1,%2,%3},{%4,%5,%6,%7},{%8,%9},{%0,%1,%2,%3};"
        :"+f"(c[0]),"+f"(c[1]),"+f"(c[2]),"+f"(c[3])
        :"r"(a0),"r"(a1),"r"(a2),"r"(a3),"r"(b0),"r"(b1));
}

// Inverse index maps (verified R9/R10)
DEVI void inv_a(int p,int&r,int&c){
    int s0=p&1, l=(p>>1)&31, hf=(p>>6)&1, ks=(p>>7)&3, rb=p>>9;
    r=rb*16+s0*8+(l>>2); c=ks*8+hf*4+(l&3);
}
DEVI void inv_b(int p,int&k,int&n){
    int s=p&1, l=(p>>1)&31, ks=(p>>6)&3, nb=p>>8;
    n=nb*8+(l>>2); k=ks*8+(s<<2)+(l&3);
}
DEVI void inv_ah(int p,int&r,int&c){
    int s=p&3, l=(p>>2)&31, ks=(p>>7)&3, rb=p>>9;
    r=rb*16+(s&1)*8+(l>>2); c=ks*8+((s>>1)<<2)+(l&3);
}

// 3-pass split chunk, MI=2, NJ templated (pass-major) — verified R9/R10
template<int NJ>
DEVI void chunk_mma(const uint4* __restrict__ A4,const uint4* __restrict__ B4,
                    int wy,int wx,int lane,float acc[2][NJ][4]){
#pragma unroll
    for(int ks=0;ks<4;ks++){
        uint4 a[2][2], b[NJ];
#pragma unroll
        for(int mi=0;mi<2;mi++){
            const uint4* ap=A4+((wy*2+mi)*4+ks)*64+lane;
            a[mi][0]=ap[0]; a[mi][1]=ap[32];
        }
#pragma unroll
        for(int nj=0;nj<NJ;nj++) b[nj]=B4[((wx*NJ+nj)*4+ks)*32+lane];
#pragma unroll
        for(int mi=0;mi<2;mi++)
#pragma unroll
            for(int nj=0;nj<NJ;nj++)
                mma8(acc[mi][nj],a[mi][0].x,a[mi][0].z,a[mi][1].x,a[mi][1].z,b[nj].x,b[nj].z);
#pragma unroll
        for(int mi=0;mi<2;mi++)
#pragma unroll
            for(int nj=0;nj<NJ;nj++)
                mma8(acc[mi][nj],a[mi][0].y,a[mi][0].w,a[mi][1].y,a[mi][1].w,b[nj].x,b[nj].z);
#pragma unroll
        for(int mi=0;mi<2;mi++)
#pragma unroll
            for(int nj=0;nj<NJ;nj++)
                mma8(acc[mi][nj],a[mi][0].x,a[mi][0].z,a[mi][1].x,a[mi][1].z,b[nj].y,b[nj].w);
    }
}
// 1-pass hi chunk
template<int NJ>
DEVI void chunk_mma_hi(const uint4* __restrict__ A4,const uint2* __restrict__ B2,
                       int wy,int wx,int lane,float acc[2][NJ][4]){
#pragma unroll
    for(int ks=0;ks<4;ks++){
        uint4 a[2]; uint2 b[NJ];
#pragma unroll
        for(int mi=0;mi<2;mi++) a[mi]=A4[((wy*2+mi)*4+ks)*32+lane];
#pragma unroll
        for(int nj=0;nj<NJ;nj++) b[nj]=B2[((wx*NJ+nj)*4+ks)*32+lane];
#pragma unroll
        for(int mi=0;mi<2;mi++)
#pragma unroll
            for(int nj=0;nj<NJ;nj++)
                mma8(acc[mi][nj],a[mi].x,a[mi].y,a[mi].z,a[mi].w,b[nj].x,b[nj].y);
    }
}

template<int NJ,int STRIDE>
DEVI void acc2ep(float* ep,int wy,int wx,int lane,float acc[2][NJ][4]){
#pragma unroll
    for(int mi=0;mi<2;mi++)
#pragma unroll
        for(int nj=0;nj<NJ;nj++){
            int r=wy*32+(lane>>2)+mi*16, c=wx*(NJ*8)+nj*8+(lane&3)*2;
            ep[r*STRIDE+c]=acc[mi][nj][0];     ep[r*STRIDE+c+1]=acc[mi][nj][1];
            ep[(r+8)*STRIDE+c]=acc[mi][nj][2]; ep[(r+8)*STRIDE+c+1]=acc[mi][nj][3];
        }
}

// ------------------------- pack kernels -------------------------
__global__ void pack_x(const float* __restrict__ q,const float* __restrict__ k){
    __shared__ float t[64][36];
    const float* src=blockIdx.z==0?q:k;
    const int m0=blockIdx.y, k0=blockIdx.x, tid=threadIdx.x;
#pragma unroll
    for(int i=0;i<2;i++){
        int r=(tid>>3)+i*32, c4=(tid&7)<<2;
        float4 x=*(const float4*)(src+(size_t)(m0*64+r)*512+k0*32+c4);
        t[r][c4]=x.x; t[r][c4+1]=x.y; t[r][c4+2]=x.z; t[r][c4+3]=x.w;
    }
    __syncthreads();
    uint2* dst=g_xpk+((size_t)(blockIdx.z*128+m0)*16+k0)*2048;
#pragma unroll
    for(int j=0;j<8;j+=2){
        int p=tid*8+j,r,c,r1,c1;
        inv_a(p,r,c); inv_a(p+1,r1,c1);
        uint2 w0=split2(t[r][c]), w1=split2(t[r1][c1]);
        *(uint4*)(dst+p)=make_uint4(w0.x,w0.y,w1.x,w1.y);
    }
}
__global__ void pack_xh(const float* __restrict__ v){
    __shared__ float t[64][36];
    const int m0=blockIdx.y, k0=blockIdx.x, tid=threadIdx.x;
#pragma unroll
    for(int i=0;i<2;i++){
        int r=(tid>>3)+i*32, c4=(tid&7)<<2;
        float4 x=*(const float4*)(v+(size_t)(m0*64+r)*512+k0*32+c4);
        t[r][c4]=x.x; t[r][c4+1]=x.y; t[r][c4+2]=x.z; t[r][c4+3]=x.w;
    }
    __syncthreads();
    uint32_t* dst=g_xpkh+((size_t)m0*16+k0)*2048;
#pragma unroll
    for(int j=0;j<8;j+=4){
        int p=tid*8+j; uint32_t w[4];
#pragma unroll
        for(int jj=0;jj<4;jj++){ int r,c; inv_ah(p+jj,r,c); w[jj]=f2tf(t[r][c]); }
        *(uint4*)(dst+p)=make_uint4(w[0],w[1],w[2],w[3]);
    }
}
__global__ void pack_w(const float* __restrict__ Wq,const float* __restrict__ Wk){
    __shared__ float t[32][132];
    const float* W=blockIdx.z==0?Wq:Wk;
    const int k0=blockIdx.x, n0=blockIdx.y, tid=threadIdx.x;
#pragma unroll
    for(int i=0;i<4;i++){
        int idx=tid+i*256, r=idx>>5, c4=(idx&31)<<2;
        float4 x=*(const float4*)(W+(size_t)(k0*32+r)*512+n0*128+c4);
        t[r][c4]=x.x; t[r][c4+1]=x.y; t[r][c4+2]=x.z; t[r][c4+3]=x.w;
    }
    __syncthreads();
    uint2* dst=g_wpk+((size_t)(blockIdx.z*4+n0)*16+k0)*4096;
#pragma unroll
    for(int j=0;j<16;j+=2){
        int p=tid*16+j,k,n,k1,n1;
        inv_b(p,k,n); inv_b(p+1,k1,n1);
        uint2 w0=split2(t[k][n]), w1=split2(t[k1][n1]);
        *(uint4*)(dst+p)=make_uint4(w0.x,w0.y,w1.x,w1.y);
    }
}
__global__ void pack_bh(const float* __restrict__ W, uint32_t* __restrict__ dpk){
    __shared__ float t[32][132];
    const int k0=blockIdx.x, n0=blockIdx.y, tid=threadIdx.x;
#pragma unroll
    for(int i=0;i<4;i++){
        int idx=tid+i*256, r=idx>>5, c4=(idx&31)<<2;
        float4 x=*(const float4*)(W+(size_t)(k0*32+r)*512+n0*128+c4);
        t[r][c4]=x.x; t[r][c4+1]=x.y; t[r][c4+2]=x.z; t[r][c4+3]=x.w;
    }
    __syncthreads();
    uint32_t* dst=dpk+((size_t)(n0*16+k0))*4096;
#pragma unroll
    for(int j=0;j<16;j+=2){
        int p=tid*16+j,k,n,k1,n1;
        inv_b(p,k,n); inv_b(p+1,k1,n1);
        *(uint2*)(dst+p)=make_uint2(f2tf(t[k][n]),f2tf(t[k1][n1]));
    }
}
__global__ void pack_vt(){
    __shared__ float t[32][68];
    const int c0=blockIdx.x, bh=blockIdx.y, b=bh>>3, h=bh&7, tid=threadIdx.x;
#pragma unroll
    for(int i=0;i<2;i++){
        int idx=tid+i*256, r=idx>>4, c4=(idx&15)<<2;
        float4 x=*(const float4*)(g_vhf+(size_t)(b*1024+c0*32+r)*512+h*64+c4);
        t[r][c4]=x.x; t[r][c4+1]=x.y; t[r][c4+2]=x.z; t[r][c4+3]=x.w;
    }
    __syncthreads();
    uint32_t* dst=g_vpkh+((size_t)bh*32+c0)*2048;
#pragma unroll
    for(int j=0;j<8;j+=2){
        int p=tid*8+j,k,n,k1,n1;
        inv_b(p,k,n); inv_b(p+1,k1,n1);
        *(uint2*)(dst+p)=make_uint2(f2tf(t[k][n]),f2tf(t[k1][n1]));
    }
}

// ------------------------- proj_qk (q,k @ W), 3-pass, 512 thr -------------------------
__global__ __launch_bounds__(512,2) void proj_qk(){
    extern __shared__ __align__(16) char sm[];
    const int tid=threadIdx.x, lane=tid&31, warp=tid>>5, wy=warp>>3, wx=warp&7;
    const int bx=blockIdx.x, by=blockIdx.y, z=blockIdx.z;
    const uint32_t smb=s2u(sm);
    const uint4* Ag=(const uint4*)g_xpk+((size_t)(z*128+by)*16)*1024;
    const uint4* Bg=(const uint4*)g_wpk+((size_t)(z*4+bx)*16)*2048;
    float acc[2][2][4];
#pragma unroll
    for(int i=0;i<2;i++)
#pragma unroll
        for(int j=0;j<2;j++)
#pragma unroll
            for(int q2=0;q2<4;q2++) acc[i][j][q2]=0.f;
    auto stage=[&](int c,int bs){
        uint32_t Ad=smb+bs*49152, Bd=Ad+16384;
#pragma unroll
        for(int i=0;i<2;i++) cp16(Ad+(tid+i*512)*16, Ag+(size_t)c*1024+tid+i*512);
#pragma unroll
        for(int i=0;i<4;i++) cp16(Bd+(tid+i*512)*16, Bg+(size_t)c*2048+tid+i*512);
        CPC();
    };
    stage(0,0); CPW(); __syncthreads();
    for(int c=0;c<16;c++){
        if(c<15) stage(c+1,(c+1)&1);
        chunk_mma<2>((const uint4*)(sm+(c&1)*49152),(const uint4*)(sm+(c&1)*49152+16384),wy,wx,lane,acc);
        CPW(); __syncthreads();
    }
    float* ep=(float*)sm;
    acc2ep<2,132>(ep,wy,wx,lane,acc);
    __syncthreads();
    const int b=by>>4, t0=(by&15)*64, h0=bx*2;
    if(tid<128){
        int r=tid&63, hl=tid>>6;
        float s=0.f;
#pragma unroll
        for(int j=0;j<64;j++){float vv=ep[r*132+hl*64+j]; s=fmaf(vv,vv,s);}
        (z==0?g_q2:g_k2)[(size_t)(b*8+h0+hl)*1024+t0+r]=s;
    }
    if(z==0){
#pragma unroll
        for(int ch=0;ch<4;ch++){
            int hl=ch>>1, kk=ch&1;
            uint2* dst=g_qpk+(((size_t)(b*8+h0+hl)*16+(by&15))*2+kk)*2048;
#pragma unroll
            for(int j=0;j<4;j+=2){
                int p=tid*4+j,r,c,r1,c1;
                inv_a(p,r,c); inv_a(p+1,r1,c1);
                uint2 w0=split2(ep[r*132+hl*64+kk*32+c]);
                uint2 w1=split2(ep[r1*132+hl*64+kk*32+c1]);
                *(uint4*)(dst+p)=make_uint4(w0.x,w0.y,w1.x,w1.y);
            }
        }
    } else {
        const int n0=t0>>7, hs=(t0>>6)&1;
#pragma unroll
        for(int ch=0;ch<4;ch++){
            int hl=ch>>1, kk=ch&1;
            uint2* dst=g_kpk+(((size_t)(b*8+h0+hl)*8+n0)*2+kk)*4096+hs*2048;
#pragma unroll
            for(int j=0;j<4;j+=2){
                int p=tid*4+j,k,n,k1,n1;
                inv_b(p,k,n); inv_b(p+1,k1,n1);
                uint2 w0=split2(ep[n*132+hl*64+kk*32+k]);
                uint2 w1=split2(ep[n1*132+hl*64+kk*32+k1]);
                *(uint4*)(dst+p)=make_uint4(w0.x,w0.y,w1.x,w1.y);
            }
        }
    }
}

// ------------------------- proj_v: vh = v @ Wv, hi 1-pass -------------------------
__global__ __launch_bounds__(256,4) void proj_v(){
    extern __shared__ __align__(16) char sm[];
    const int tid=threadIdx.x, lane=tid&31, warp=tid>>5, wy=warp>>2, wx=warp&3;
    const int bx=blockIdx.x, by=blockIdx.y;
    const uint32_t smb=s2u(sm);
    const uint4* Ag=(const uint4*)g_xpkh+((size_t)by*16)*512;
    const uint4* Bg=(const uint4*)g_wvhpk+((size_t)bx*16)*1024;
    float acc[2][4][4];
#pragma unroll
    for(int i=0;i<2;i++)
#pragma unroll
        for(int j=0;j<4;j++)
#pragma unroll
            for(int q2=0;q2<4;q2++) acc[i][j][q2]=0.f;
    auto stage=[&](int c,int bs){
        uint32_t Ad=smb+bs*8192, Bd=smb+16384+bs*16384;
#pragma unroll
        for(int i=0;i<2;i++) cp16(Ad+(tid+i*256)*16, Ag+(size_t)c*512+tid+i*256);
#pragma unroll
        for(int i=0;i<4;i++) cp16(Bd+(tid+i*256)*16, Bg+(size_t)c*1024+tid+i*256);
        CPC();
    };
    stage(0,0); CPW(); __syncthreads();
    for(int c=0;c<16;c++){
        if(c<15) stage(c+1,(c+1)&1);
        chunk_mma_hi<4>((const uint4*)(sm+(c&1)*8192),(const uint2*)(sm+16384+(c&1)*16384),wy,wx,lane,acc);
        CPW(); __syncthreads();
    }
    float* ep=(float*)sm;
    acc2ep<4,132>(ep,wy,wx,lane,acc);
    __syncthreads();
#pragma unroll
    for(int i=0;i<8;i++){
        int idx=tid+i*256, r=idx>>5, c4=(idx&31)<<2;
        *(float4*)(g_vhf+(size_t)(by*64+r)*512+bx*128+c4)=*(float4*)&ep[r*132+c4];
    }
}

// ------------------------- rbf (3-pass, 512 thr) -------------------------
__global__ __launch_bounds__(512,2) void rbf_tc(float* __restrict__ wts){
    extern __shared__ __align__(16) char sm[];
    const int tid=threadIdx.x, lane=tid&31, warp=tid>>5, wy=warp>>3, wx=warp&7;
    const int kt=blockIdx.x, qt=blockIdx.y, bh=blockIdx.z;
    const uint32_t smb=s2u(sm);
    float* q2s=(float*)(sm+98304); float* k2s=q2s+64;
    const uint4* Ag=(const uint4*)g_qpk+((size_t)(bh*16+qt)*2)*1024;
    const uint4* Bg=(const uint4*)g_kpk+((size_t)(bh*8+kt)*2)*2048;
#pragma unroll
    for(int kk=0;kk<2;kk++){
#pragma unroll
        for(int i=0;i<2;i++) cp16(smb+kk*16384+(tid+i*512)*16, Ag+(size_t)kk*1024+tid+i*512);
#pragma unroll
        for(int i=0;i<4;i++) cp16(smb+32768+kk*32768+(tid+i*512)*16, Bg+(size_t)kk*2048+tid+i*512);
    }
    CPC();
    if(tid<64) q2s[tid]=g_q2[(size_t)bh*1024+qt*64+tid];
    else if(tid<192) k2s[tid-64]=g_k2[(size_t)bh*1024+kt*128+tid-64];
    CPW(); __syncthreads();
    float acc[2][2][4];
#pragma unroll
    for(int i=0;i<2;i++)
#pragma unroll
        for(int j=0;j<2;j++)
#pragma unroll
            for(int q2=0;q2<4;q2++) acc[i][j][q2]=0.f;
    chunk_mma<2>((const uint4*)sm,(const uint4*)(sm+32768),wy,wx,lane,acc);
    chunk_mma<2>((const uint4*)(sm+16384),(const uint4*)(sm+65536),wy,wx,lane,acc);
#pragma unroll
    for(int mi=0;mi<2;mi++)
#pragma unroll
        for(int nj=0;nj<2;nj++){
            int r=wy*32+(lane>>2)+mi*16, c=wx*16+nj*8+(lane&3)*2;
            acc[mi][nj][0]=__expf(2.f*acc[mi][nj][0]-q2s[r]-k2s[c]);
            acc[mi][nj][1]=__expf(2.f*acc[mi][nj][1]-q2s[r]-k2s[c+1]);
            acc[mi][nj][2]=__expf(2.f*acc[mi][nj][2]-q2s[r+8]-k2s[c]);
            acc[mi][nj][3]=__expf(2.f*acc[mi][nj][3]-q2s[r+8]-k2s[c+1]);
        }
    __syncthreads();
    float* ep=(float*)sm;
    acc2ep<2,132>(ep,wy,wx,lane,acc);
    __syncthreads();
    float* wb=wts+((size_t)bh*1024+qt*64)*1024+kt*128;
#pragma unroll
    for(int i=0;i<4;i++){
        int idx=tid+i*512, r=idx>>5, c4=(idx&31)<<2;
        *(float4*)(wb+(size_t)r*1024+c4)=*(float4*)&ep[r*132+c4];
    }
}

// ------------------------- wv: att = W @ V, hi 1-pass -------------------------
__global__ __launch_bounds__(256,4) void wv_hi(const float* __restrict__ wts){
    extern __shared__ __align__(16) char sm[];
    const int tid=threadIdx.x, lane=tid&31, warp=tid>>5, wy=warp>>2, wx=warp&3;
    const int qt=blockIdx.x, bh=blockIdx.y;
    const uint32_t smb=s2u(sm);
    const float* wb=wts+((size_t)bh*1024+qt*64)*1024;
    const uint4* Bg=(const uint4*)g_vpkh+(size_t)bh*32*512;
    float acc[2][2][4];
#pragma unroll
    for(int i=0;i<2;i++)
#pragma unroll
        for(int j=0;j<2;j++)
#pragma unroll
            for(int q2=0;q2<4;q2++) acc[i][j][q2]=0.f;
    auto stage=[&](int c,int bs){
        uint32_t fd=smb+32768+bs*9216, bd=smb+16384+bs*8192;
#pragma unroll
        for(int i=0;i<2;i++){
            int idx=tid+i*256, r=idx>>3, c4=(idx&7)<<2;
            cp16(fd+(r*36+c4)*4, wb+(size_t)r*1024+c*32+c4);
            cp16(bd+idx*16, Bg+(size_t)c*512+idx);
        }
        CPC();
    };
    auto cvtA=[&](int bs){
        const float* stg=(const float*)(sm+32768+bs*9216);
        uint32_t* dst=(uint32_t*)(sm+bs*8192);
#pragma unroll
        for(int j=0;j<8;j+=4){
            int p=tid*8+j; uint32_t w[4];
#pragma unroll
            for(int jj=0;jj<4;jj++){ int r,cc; inv_ah(p+jj,r,cc); w[jj]=f2tf(stg[r*36+cc]); }
            *(uint4*)(dst+p)=make_uint4(w[0],w[1],w[2],w[3]);
        }
    };
    stage(0,0); CPW(); __syncthreads(); cvtA(0); __syncthreads();
    for(int c=0;c<32;c++){
        if(c<31) stage(c+1,(c+1)&1);
        chunk_mma_hi<2>((const uint4*)(sm+(c&1)*8192),(const uint2*)(sm+16384+(c&1)*8192),wy,wx,lane,acc);
        CPW(); __syncthreads();
        if(c<31) cvtA((c+1)&1);
        __syncthreads();
    }
    float* ep=(float*)sm;
    acc2ep<2,68>(ep,wy,wx,lane,acc);
    __syncthreads();
    const int b=bh>>3, h=bh&7;
#pragma unroll
    for(int cc=0;cc<2;cc++){
        uint32_t* dst=g_atpkh+((size_t)(b*16+qt)*16+h*2+cc)*2048;
#pragma unroll
        for(int j=0;j<8;j+=4){
            int p=tid*8+j; uint32_t w[4];
#pragma unroll
            for(int jj=0;jj<4;jj++){ int r,ccx; inv_ah(p+jj,r,ccx); w[jj]=f2tf(ep[r*68+cc*32+ccx]); }
            *(uint4*)(dst+p)=make_uint4(w[0],w[1],w[2],w[3]);
        }
    }
}

// ------------------------- outproj: out = att @ Wo, hi 1-pass -------------------------
__global__ __launch_bounds__(256,4) void outproj_hi(float* __restrict__ out){
    extern __shared__ __align__(16) char sm[];
    const int tid=threadIdx.x, lane=tid&31, warp=tid>>5, wy=warp>>2, wx=warp&3;
    const int bx=blockIdx.x, by=blockIdx.y;
    const uint32_t smb=s2u(sm);
    const uint4* Ag=(const uint4*)g_atpkh+((size_t)by*16)*512;
    const uint4* Bg=(const uint4*)g_wohpk+((size_t)bx*16)*1024;
    float acc[2][4][4];
#pragma unroll
    for(int i=0;i<2;i++)
#pragma unroll
        for(int j=0;j<4;j++)
#pragma unroll
            for(int q2=0;q2<4;q2++) acc[i][j][q2]=0.f;
    auto stage=[&](int c,int bs){
        uint32_t Ad=smb+bs*8192, Bd=smb+16384+bs*16384;
#pragma unroll
        for(int i=0;i<2;i++) cp16(Ad+(tid+i*256)*16, Ag+(size_t)c*512+tid+i*256);
#pragma unroll
        for(int i=0;i<4;i++) cp16(Bd+(tid+i*256)*16, Bg+(size_t)c*1024+tid+i*256);
        CPC();
    };
    stage(0,0); CPW(); __syncthreads();
    for(int c=0;c<16;c++){
        if(c<15) stage(c+1,(c+1)&1);
        chunk_mma_hi<4>((const uint4*)(sm+(c&1)*8192),(const uint2*)(sm+16384+(c&1)*16384),wy,wx,lane,acc);
        CPW(); __syncthreads();
    }
    float* ep=(float*)sm;
    acc2ep<4,132>(ep,wy,wx,lane,acc);
    __syncthreads();
#pragma unroll
    for(int i=0;i<8;i++){
        int idx=tid+i*256, r=idx>>5, c4=(idx&31)<<2;
        *(float4*)(out+(size_t)(by*64+r)*512+bx*128+c4)=*(float4*)&ep[r*132+c4];
    }
}

// ---------------------------------------------------------------------------
extern "C" void kernel_launch(void* const* d_in,const int* in_sizes,int n_in,
                              void* d_out,int out_size){
    (void)in_sizes; (void)n_in; (void)out_size;
    const float* q =(const float*)d_in[0];
    const float* k =(const float*)d_in[1];
    const float* v =(const float*)d_in[2];
    const float* Wq=(const float*)d_in[3];
    const float* Wk=(const float*)d_in[4];
    const float* Wv=(const float*)d_in[5];
    const float* Wo=(const float*)d_in[6];
    float* out=(float*)d_out;
    float* wts=out+OUT_ELEMS;

    void* p;
    uint32_t *wvh,*woh;
    cudaGetSymbolAddress(&p,g_wvhpk); wvh=(uint32_t*)p;
    cudaGetSymbolAddress(&p,g_wohpk); woh=(uint32_t*)p;

    cudaFuncSetAttribute(proj_qk,    cudaFuncAttributeMaxDynamicSharedMemorySize, 98304);
    cudaFuncSetAttribute(proj_v,     cudaFuncAttributeMaxDynamicSharedMemorySize, 49152);
    cudaFuncSetAttribute(rbf_tc,     cudaFuncAttributeMaxDynamicSharedMemorySize, 99072);
    cudaFuncSetAttribute(wv_hi,      cudaFuncAttributeMaxDynamicSharedMemorySize, 51200);
    cudaFuncSetAttribute(outproj_hi, cudaFuncAttributeMaxDynamicSharedMemorySize, 49152);

    pack_x<<<dim3(16,128,2),256>>>(q,k);
    pack_xh<<<dim3(16,128),256>>>(v);
    pack_w<<<dim3(16,4,2),256>>>(Wq,Wk);
    pack_bh<<<dim3(16,4),256>>>(Wv,wvh);
    pack_bh<<<dim3(16,4),256>>>(Wo,woh);
    proj_qk<<<dim3(4,128,2),512,98304>>>();
    proj_v<<<dim3(4,128),256,49152>>>();
    pack_vt<<<dim3(32,64),256>>>();
    rbf_tc<<<dim3(8,16,64),512,99072>>>(wts);
    wv_hi<<<dim3(16,64),256,51200>>>(wts);
    outproj_hi<<<dim3(4,128),256,49152>>>(out);
}